// round 9
// baseline (speedup 1.0000x reference)
#include <cuda_runtime.h>

#define BATCH    4096
#define NINTRS   256
#define NATOMS   256
#define DATA_DIM 28
#define KSTRIDE  29   // padded atoms row length in smem (odd -> conflict-free)

__device__ int g_cnt[BATCH];
__device__ int g_rowoff[BATCH];

// ---------------------------------------------------------------------------
// Mask dtype auto-detection. The harness may materialize the bool mask as
// uint8 (0x01010101 in the first word for this dataset), int32 (0x00000001),
// or float32 (0x3F800000). Deterministic: same input -> same mode.
// ---------------------------------------------------------------------------
__device__ __forceinline__ unsigned mask_mode(const void* m) {
    unsigned w0 = *reinterpret_cast<const unsigned*>(m);
    if (w0 == 0x3F800000u) return 2u;   // float32
    if (w0 == 1u)          return 1u;   // int32
    return 0u;                          // byte / bool
}

__device__ __forceinline__ int mask_at(const void* m, unsigned mode, long i) {
    if (mode == 1u) return reinterpret_cast<const int*>(m)[i] != 0;
    if (mode == 2u) return reinterpret_cast<const float*>(m)[i] != 0.0f;
    return reinterpret_cast<const unsigned char*>(m)[i] != 0;
}

// ---------------------------------------------------------------------------
// Kernel A: per-ray valid count (one warp per ray), dtype-generic.
// ---------------------------------------------------------------------------
__global__ void count_kernel(const void* __restrict__ mask) {
    unsigned mode = mask_mode(mask);
    int ray  = blockIdx.x * 8 + (threadIdx.x >> 5);
    int lane = threadIdx.x & 31;
    long base = (long)ray * NINTRS + (long)lane * 8;
    int s = 0;
    #pragma unroll
    for (int e = 0; e < 8; e++) s += mask_at(mask, mode, base + e);
    #pragma unroll
    for (int o = 16; o; o >>= 1) s += __shfl_down_sync(0xffffffffu, s, o);
    if (lane == 0) g_cnt[ray] = s;
}

// ---------------------------------------------------------------------------
// Kernel B: exclusive scan of per-ray counts -> row offsets into `queries`.
// ---------------------------------------------------------------------------
__global__ void scan_kernel() {
    __shared__ int sh[1024];
    int t = threadIdx.x;
    int a[4];
    int s = 0;
    #pragma unroll
    for (int j = 0; j < 4; j++) { a[j] = s; s += g_cnt[t * 4 + j]; }
    sh[t] = s;
    __syncthreads();
    for (int off = 1; off < 1024; off <<= 1) {
        int v = (t >= off) ? sh[t - off] : 0;
        __syncthreads();
        sh[t] += v;
        __syncthreads();
    }
    int excl = sh[t] - s;
    #pragma unroll
    for (int j = 0; j < 4; j++) g_rowoff[t * 4 + j] = excl + a[j];
}

// ---------------------------------------------------------------------------
// Main fused kernel: one CTA per ray, 256 threads.
//   1. stage atoms (256x28) in padded smem
//   2. SH basis + per-ray reduced matrix Bred[256] = (r,g,b,sigma)
//   3. warp-per-row GEMM: queries_row(256) . Bred -> res[j]
//   4. alpha, product-scan transmittance, sigmoid-RGB / depth reductions
// ---------------------------------------------------------------------------
__global__ void __launch_bounds__(256)
render_kernel(const float* __restrict__ rays_d,
              const float* __restrict__ queries,
              const void*  __restrict__ mask,
              const float* __restrict__ inter,
              const float* __restrict__ atoms,
              float* __restrict__ out_rgb,
              float* __restrict__ out_alpha,
              float* __restrict__ out_depth)
{
    __shared__ float s_pool[NATOMS * KSTRIDE + NATOMS * 4];  // satoms | Bred
    __shared__ float s_sh[10];                               // sh[9], dnorm
    __shared__ int   s_wcnt[8];
    __shared__ float s_wprod[8];
    __shared__ float s_red[5][8];

    float*  satoms = s_pool;
    float4* Bred   = reinterpret_cast<float4*>(s_pool + NATOMS * KSTRIDE);
    float4* res    = reinterpret_cast<float4*>(s_pool);  // reuses satoms after Bred built

    const int b    = blockIdx.x;
    const int tid  = threadIdx.x;
    const int lane = tid & 31;
    const int wid  = tid >> 5;

    // ---- 1. stage atoms into padded smem ----
    #pragma unroll
    for (int it = 0; it < (NATOMS * DATA_DIM) / 256; it++) {
        int idx = tid + it * 256;
        int r = idx / DATA_DIM;
        int c = idx - r * DATA_DIM;
        satoms[r * KSTRIDE + c] = atoms[idx];
    }

    // ---- SH basis + ray norm ----
    if (tid == 0) {
        float dx = rays_d[b * 3 + 0], dy = rays_d[b * 3 + 1], dz = rays_d[b * 3 + 2];
        float n = sqrtf(dx * dx + dy * dy + dz * dz);
        float inv = 1.0f / n;
        float x = dx * inv, y = dy * inv, z = dz * inv;
        const float C0 = 0.28209479177387814f;
        const float C1 = 0.4886025119029199f;
        s_sh[0] = C0;
        s_sh[1] = -C1 * y;
        s_sh[2] =  C1 * z;
        s_sh[3] = -C1 * x;
        s_sh[4] =  1.0925484305920792f * x * y;
        s_sh[5] = -1.0925484305920792f * y * z;
        s_sh[6] =  0.31539156525252005f * (2.0f * z * z - x * x - y * y);
        s_sh[7] = -1.0925484305920792f * x * z;
        s_sh[8] =  0.5462742152960396f * (x * x - y * y);
        s_sh[9] = n;
    }
    __syncthreads();

    // ---- 2. per-ray reduced matrix: thread k handles atoms row k ----
    {
        const float* ar = satoms + tid * KSTRIDE;
        float c0 = 0.f, c1 = 0.f, c2 = 0.f;
        #pragma unroll
        for (int s = 0; s < 9; s++) {
            float bs = s_sh[s];
            c0 = fmaf(bs, ar[s],      c0);
            c1 = fmaf(bs, ar[9 + s],  c1);
            c2 = fmaf(bs, ar[18 + s], c2);
        }
        Bred[tid] = make_float4(c0, c1, c2, ar[27]);
    }

    // ---- mask + compaction rank (dtype-generic) ----
    const unsigned mmode = mask_mode(mask);
    const int mbit = mask_at(mask, mmode, (long)b * NINTRS + tid);
    unsigned bal = __ballot_sync(0xffffffffu, (unsigned)mbit);
    int lprefix = __popc(bal & ((1u << lane) - 1u));
    if (lane == 0) s_wcnt[wid] = __popc(bal);
    __syncthreads();

    int woff = 0, cnt_b = 0;
    #pragma unroll
    for (int w = 0; w < 8; w++) {
        int c = s_wcnt[w];
        if (w < wid) woff += c;
        cnt_b += c;
    }
    const int local_pos = woff + lprefix;
    const int rowbase   = g_rowoff[b];

    // ---- register slice of Bred ----
    float4 Bt[8];
    #pragma unroll
    for (int j = 0; j < 4; j++) Bt[j]     = Bred[lane * 4 + j];
    #pragma unroll
    for (int j = 0; j < 4; j++) Bt[4 + j] = Bred[128 + lane * 4 + j];

    // ---- 3. GEMM: warp `wid` handles rows wid, wid+8, ... ----
    const float4* qbase = reinterpret_cast<const float4*>(queries);
    {
        int j = wid;
        float4 qa = make_float4(0.f, 0.f, 0.f, 0.f), qb = qa;
        if (j < cnt_b) {
            const float4* q = qbase + (size_t)(rowbase + j) * (NATOMS / 4);
            qa = q[lane]; qb = q[lane + 32];
        }
        while (j < cnt_b) {
            int jn = j + 8;
            float4 na = make_float4(0.f, 0.f, 0.f, 0.f), nb = na;
            if (jn < cnt_b) {
                const float4* q = qbase + (size_t)(rowbase + jn) * (NATOMS / 4);
                na = q[lane]; nb = q[lane + 32];
            }
            float4 acc = make_float4(0.f, 0.f, 0.f, 0.f);
            #define ACC4(qv, bt) { \
                acc.x = fmaf(qv, bt.x, acc.x); acc.y = fmaf(qv, bt.y, acc.y); \
                acc.z = fmaf(qv, bt.z, acc.z); acc.w = fmaf(qv, bt.w, acc.w); }
            ACC4(qa.x, Bt[0]); ACC4(qa.y, Bt[1]); ACC4(qa.z, Bt[2]); ACC4(qa.w, Bt[3]);
            ACC4(qb.x, Bt[4]); ACC4(qb.y, Bt[5]); ACC4(qb.z, Bt[6]); ACC4(qb.w, Bt[7]);
            #undef ACC4
            #pragma unroll
            for (int o = 16; o; o >>= 1) {
                acc.x += __shfl_down_sync(0xffffffffu, acc.x, o);
                acc.y += __shfl_down_sync(0xffffffffu, acc.y, o);
                acc.z += __shfl_down_sync(0xffffffffu, acc.z, o);
                acc.w += __shfl_down_sync(0xffffffffu, acc.w, o);
            }
            if (lane == 0) res[j] = acc;
            qa = na; qb = nb;
            j = jn;
        }
    }
    __syncthreads();

    // ---- 4. rendering: thread i = intersection i ----
    float4 r4 = make_float4(0.f, 0.f, 0.f, 0.f);
    if (mbit) r4 = res[local_pos];
    float sigma = fmaxf(r4.w, 0.0f);
    const float dn = s_sh[9];
    const float* ib = inter + (size_t)b * (NINTRS + 1);
    float t0 = ib[tid], t1 = ib[tid + 1];
    float delta = t1 - t0;
    float alpha = 1.0f - expf(-sigma * delta * dn);
    float p = 1.0f - alpha + 1e-10f;

    // exclusive product scan -> transmittance
    float incl = p;
    #pragma unroll
    for (int o = 1; o < 32; o <<= 1) {
        float v = __shfl_up_sync(0xffffffffu, incl, o);
        if (lane >= o) incl *= v;
    }
    if (lane == 31) s_wprod[wid] = incl;
    float prev = __shfl_up_sync(0xffffffffu, incl, 1);
    float excl_w = (lane == 0) ? 1.0f : prev;
    __syncthreads();
    float wpre = 1.0f;
    #pragma unroll
    for (int w = 0; w < 8; w++) if (w < wid) wpre *= s_wprod[w];
    float trans = wpre * excl_w;
    float wgt = alpha * trans;  // abs_light

    float sgx = 1.0f / (1.0f + expf(-r4.x));
    float sgy = 1.0f / (1.0f + expf(-r4.y));
    float sgz = 1.0f / (1.0f + expf(-r4.z));
    float tmid = 0.5f * (t0 + t1);

    float v0 = wgt;
    float v1 = wgt * sgx;
    float v2 = wgt * sgy;
    float v3 = wgt * sgz;
    float v4 = wgt * tmid;
    #pragma unroll
    for (int o = 16; o; o >>= 1) {
        v0 += __shfl_down_sync(0xffffffffu, v0, o);
        v1 += __shfl_down_sync(0xffffffffu, v1, o);
        v2 += __shfl_down_sync(0xffffffffu, v2, o);
        v3 += __shfl_down_sync(0xffffffffu, v3, o);
        v4 += __shfl_down_sync(0xffffffffu, v4, o);
    }
    if (lane == 0) {
        s_red[0][wid] = v0; s_red[1][wid] = v1; s_red[2][wid] = v2;
        s_red[3][wid] = v3; s_red[4][wid] = v4;
    }
    __syncthreads();
    if (tid == 0) {
        float S = 0.f, R0 = 0.f, R1 = 0.f, R2 = 0.f, D = 0.f;
        #pragma unroll
        for (int w = 0; w < 8; w++) {
            S  += s_red[0][w]; R0 += s_red[1][w]; R1 += s_red[2][w];
            R2 += s_red[3][w]; D  += s_red[4][w];
        }
        float bg = 1.0f - S;  // white background
        out_rgb[b * 3 + 0] = R0 + bg;
        out_rgb[b * 3 + 1] = R1 + bg;
        out_rgb[b * 3 + 2] = R2 + bg;
        out_depth[b] = D;
    }
    out_alpha[(size_t)b * NINTRS + tid] = alpha;
}

// ---------------------------------------------------------------------------
// Launch. Inputs are bound BY ELEMENT COUNT (all five are distinct), making
// the kernel immune to metadata ordering:
//   rays_d        : 4096*3        = 12288
//   queries       : 524288*256    = 134217728
//   queries_mask  : 4096*256      = 1048576
//   intersections : 4096*257      = 1052672
//   atoms         : 256*28        = 7168
// Output: concat(rgb[4096,3], alpha[4096,256], depth[4096]) as f32.
// ---------------------------------------------------------------------------
extern "C" void kernel_launch(void* const* d_in, const int* in_sizes, int n_in,
                              void* d_out, int out_size) {
    const float* rays_d  = nullptr;
    const float* queries = nullptr;
    const void*  qmask   = nullptr;
    const float* inter   = nullptr;
    const float* atoms   = nullptr;

    for (int i = 0; i < n_in; i++) {
        switch (in_sizes[i]) {
            case 12288:      rays_d  = (const float*)d_in[i]; break;
            case 134217728:  queries = (const float*)d_in[i]; break;
            case 1048576:    qmask   = d_in[i];               break;
            case 1052672:    inter   = (const float*)d_in[i]; break;
            case 7168:       atoms   = (const float*)d_in[i]; break;
            default: break;
        }
    }

    float* out       = (float*)d_out;
    float* out_rgb   = out;
    float* out_alpha = out + BATCH * 3;
    float* out_depth = out + BATCH * 3 + (size_t)BATCH * NINTRS;

    count_kernel<<<BATCH / 8, 256>>>(qmask);
    scan_kernel<<<1, 1024>>>();
    render_kernel<<<BATCH, 256>>>(rays_d, queries, qmask, inter, atoms,
                                  out_rgb, out_alpha, out_depth);
}